// round 5
// baseline (speedup 1.0000x reference)
#include <cuda_runtime.h>
#include <math.h>
#include <stdint.h>

// ---------------------------------------------------------------------------
// Problem constants
// ---------------------------------------------------------------------------
#define BATCH   65536
#define DIN     118
#define NS      128          // ODE state dim (118 + 10 aug)
#define NH      256          // hidden dim
#define NOUTC   10           // output dim
#define NEL     (BATCH*NS)   // 8388608 state elements
#define ROWS_PB 64           // batch rows per tile
#define NTILES  (BATCH/ROWS_PB)   // 1024 tiles
#define NBLOCKS 148          // persistent blocks, 1 per SM (GB300 has 152 SMs)
#define MAXIT   20           // attempt safety bound (while-loop breaks early)
#define RTOLv   1e-3f
#define ATOLv   1e-3f
#define LDA     68           // smem K-major row stride (64 rows + 4 pad)
#define KCH     16           // K chunk staged through smem (duplicated pairs)

// smem: A_T[128][LDA] + H1_T[256][LDA] + H2_T[256][LDA] + Bs_dup[KCH][256][2]
#define SMEM_FLOATS (128*LDA + 256*LDA + 256*LDA + KCH*256*2)
#define SMEM_BYTES  (SMEM_FLOATS*4)

// ---------------------------------------------------------------------------
// Device global scratch
// ---------------------------------------------------------------------------
__device__ float g_ybuf[2][NEL];   // double-buffered state y
__device__ float g_k[7][NEL];      // RK stages; slots {0,6} swap as k1/k7 (FSAL)

struct Ctrl {
    double sum0, sum1, sum2, errsum;
    float  t, dt, dt_last, last_t, h0, d1;
    int    done, cur, k0slot;
};
__device__ Ctrl g_ctrl;
#define VC ((volatile Ctrl*)&g_ctrl)

// grid barrier state (sense-reversal via phase counter; persists across runs
// harmlessly since the barrier is phase-relative)
__device__ unsigned g_bar_count = 0;
__device__ volatile unsigned g_bar_phase = 0;

__device__ __forceinline__ void grid_barrier() {
    __syncthreads();
    if (threadIdx.x == 0) {
        unsigned ph = g_bar_phase;
        __threadfence();
        if (atomicAdd(&g_bar_count, 1u) == NBLOCKS - 1) {
            g_bar_count = 0;
            __threadfence();
            g_bar_phase = ph + 1;
        } else {
            while (g_bar_phase == ph) { }
        }
        __threadfence();
    }
    __syncthreads();
}

// ---------------------------------------------------------------------------
// Dopri5 tableau (exactly as jax.experimental.ode, double -> float)
// ---------------------------------------------------------------------------
__constant__ float c_beta[6][6] = {
    {(float)(1.0/5.0), 0.f, 0.f, 0.f, 0.f, 0.f},
    {(float)(3.0/40.0), (float)(9.0/40.0), 0.f, 0.f, 0.f, 0.f},
    {(float)(44.0/45.0), (float)(-56.0/15.0), (float)(32.0/9.0), 0.f, 0.f, 0.f},
    {(float)(19372.0/6561.0), (float)(-25360.0/2187.0), (float)(64448.0/6561.0),
     (float)(-212.0/729.0), 0.f, 0.f},
    {(float)(9017.0/3168.0), (float)(-355.0/33.0), (float)(46732.0/5247.0),
     (float)(49.0/176.0), (float)(-5103.0/18656.0), 0.f},
    {(float)(35.0/384.0), 0.f, (float)(500.0/1113.0), (float)(125.0/192.0),
     (float)(-2187.0/6784.0), (float)(11.0/84.0)}
};
__constant__ float c_errv[7] = {
    (float)(35.0/384.0 - 1951.0/21600.0), 0.f,
    (float)(500.0/1113.0 - 22642.0/50085.0),
    (float)(125.0/192.0 - 451.0/720.0),
    (float)(-2187.0/6784.0 + 12231.0/42400.0),
    (float)(11.0/84.0 - 649.0/6300.0),
    (float)(-1.0/60.0)
};
__constant__ float c_midv[7] = {
    (float)(6025192743.0/30085553152.0/2.0), 0.f,
    (float)(51252292925.0/65400821598.0/2.0),
    (float)(-2691868925.0/45128329728.0/2.0),
    (float)(187940372067.0/1594534317056.0/2.0),
    (float)(-1776094331.0/19743644256.0/2.0),
    (float)(11237099.0/235043384.0/2.0)
};

// ---------------------------------------------------------------------------
// f32x2 packed-FMA helpers
// ---------------------------------------------------------------------------
__device__ __forceinline__ void fma2(unsigned long long &d,
                                     unsigned long long a,
                                     unsigned long long b) {
    asm("fma.rn.f32x2 %0, %1, %2, %0;" : "+l"(d) : "l"(a), "l"(b));
}
__device__ __forceinline__ float2 unpack2(unsigned long long v) {
    float2 r;
    asm("mov.b64 {%0, %1}, %2;" : "=f"(r.x), "=f"(r.y) : "l"(v));
    return r;
}

// ---------------------------------------------------------------------------
// Layer with NOUTL=256 output cols (layers 1 and 2), duplicated-B smem.
// Thread map: tx = tid&7 -> 8-row group, ty = tid>>3 -> 8-col group.
// ---------------------------------------------------------------------------
template<int KD, bool RELU>
__device__ __forceinline__ void mlp_layer256(
    const float* __restrict__ At,    // smem [KD][LDA] K-major
    const float* __restrict__ Wg,    // global [KD][256] row-major
    const float* __restrict__ bias,
    float* __restrict__ Bs,          // smem dup staging [KCH][256][2]
    float* __restrict__ OutT)        // smem K-major out [256][LDA]
{
    constexpr int NOUTL = 256, CW = 8;
    const int tid = threadIdx.x;
    const int tx  = tid & 7;
    const int ty  = tid >> 3;

    unsigned long long acc[CW][4] = {};

    #pragma unroll 1
    for (int kh = 0; kh < KD; kh += KCH) {
        // stage W chunk duplicated: Bs[k][col] = {w, w}
        #pragma unroll
        for (int i = tid; i < KCH*NOUTL/4; i += 256) {
            int kr = i >> 6, c4 = (i & 63) << 2;
            float4 w = *(const float4*)(Wg + (size_t)(kh + kr)*NOUTL + c4);
            float* dst = Bs + ((kr << 8) + c4)*2;
            *(float4*)(dst)     = make_float4(w.x, w.x, w.y, w.y);
            *(float4*)(dst + 4) = make_float4(w.z, w.z, w.w, w.w);
        }
        __syncthreads();

        #pragma unroll
        for (int k = 0; k < KCH; ++k) {
            const float* arow = At + (kh + k)*LDA + tx*8;
            ulonglong2 a01 = *(const ulonglong2*)arow;
            ulonglong2 a23 = *(const ulonglong2*)(arow + 4);
            unsigned long long av[4] = {a01.x, a01.y, a23.x, a23.y};
            const float* brow = Bs + ((k << 8) + ty*CW)*2;
            #pragma unroll
            for (int cp = 0; cp < 4; ++cp) {
                ulonglong2 bd = *(const ulonglong2*)(brow + cp*4);
                #pragma unroll
                for (int r = 0; r < 4; ++r) {
                    fma2(acc[2*cp  ][r], av[r], bd.x);
                    fma2(acc[2*cp+1][r], av[r], bd.y);
                }
            }
        }
        __syncthreads();
    }

    #pragma unroll
    for (int c = 0; c < CW; ++c) {
        int col = ty*CW + c;
        float bj = bias[col];
        float2 p0 = unpack2(acc[c][0]);
        float2 p1 = unpack2(acc[c][1]);
        float2 p2 = unpack2(acc[c][2]);
        float2 p3 = unpack2(acc[c][3]);
        float4 v0 = {p0.x + bj, p0.y + bj, p1.x + bj, p1.y + bj};
        float4 v1 = {p2.x + bj, p2.y + bj, p3.x + bj, p3.y + bj};
        if (RELU) {
            v0.x = fmaxf(v0.x, 0.f); v0.y = fmaxf(v0.y, 0.f);
            v0.z = fmaxf(v0.z, 0.f); v0.w = fmaxf(v0.w, 0.f);
            v1.x = fmaxf(v1.x, 0.f); v1.y = fmaxf(v1.y, 0.f);
            v1.z = fmaxf(v1.z, 0.f); v1.w = fmaxf(v1.w, 0.f);
        }
        *(float4*)(OutT + col*LDA + tx*8)     = v0;
        *(float4*)(OutT + col*LDA + tx*8 + 4) = v1;
    }
}

// ---------------------------------------------------------------------------
// Full stage for one 64-row tile: build yi = y + dt*sum(beta*k) in smem,
// run 3 MLP layers, write k_out; stage 6 also writes y1 and accumulates the
// per-element error ratio (fused err_reduce).
//  stage = -1 : f0 eval (yi = y)
//  stage = -2 : init probe (yi = y + h0*f0), out slot 1
//  stage = 1..6
// ---------------------------------------------------------------------------
__device__ void tile_stage(
    int stage, int tile, int cur, int k0s, float dt, float h0,
    const float* __restrict__ W1, const float* __restrict__ b1,
    const float* __restrict__ W2, const float* __restrict__ b2,
    const float* __restrict__ W3, const float* __restrict__ b3,
    float* sm, double& errloc)
{
    float* A_T  = sm;                       // [128][LDA]  (holds y1 for stage 6)
    float* H1_T = sm + 128*LDA;             // [256][LDA]
    float* H2_T = H1_T + 256*LDA;           // [256][LDA]
    float* Bs   = H2_T + 256*LDA;           // [KCH][NOUTL][2]

    const int tid  = threadIdx.x;
    const int row0 = tile * ROWS_PB;
    const float* y = g_ybuf[cur];
    float* ynext   = g_ybuf[cur ^ 1];

    const float* kparr[6];
    kparr[0] = g_k[k0s];
    kparr[1] = g_k[1]; kparr[2] = g_k[2]; kparr[3] = g_k[3];
    kparr[4] = g_k[4]; kparr[5] = g_k[5];

    float coef[6];
    int nk, outslot;
    if (stage == -1)      { nk = 0; outslot = k0s; }
    else if (stage == -2) { nk = 1; coef[0] = h0; outslot = 1; }
    else {
        nk = stage;
        #pragma unroll
        for (int j = 0; j < 6; ++j) coef[j] = dt * c_beta[stage-1][j];
        outslot = (stage < 6) ? stage : (k0s ^ 6);
    }
    float* kout = g_k[outslot];

    // phase 0: stage input -> A_T (K-major); stage 6 also emits y1
    for (int i = tid; i < ROWS_PB*NS/4; i += 256) {
        int r  = i >> 5;
        int c4 = i & 31;
        size_t g4 = ((size_t)(row0 + r)*NS >> 2) + c4;
        float4 v = ((const float4*)y)[g4];
        for (int j = 0; j < nk; ++j) {
            float4 kv = ((const float4*)kparr[j])[g4];
            v.x = fmaf(coef[j], kv.x, v.x);
            v.y = fmaf(coef[j], kv.y, v.y);
            v.z = fmaf(coef[j], kv.z, v.z);
            v.w = fmaf(coef[j], kv.w, v.w);
        }
        if (stage == 6) ((float4*)ynext)[g4] = v;
        int cc = c4 * 4;
        A_T[(cc+0)*LDA + r] = v.x;
        A_T[(cc+1)*LDA + r] = v.y;
        A_T[(cc+2)*LDA + r] = v.z;
        A_T[(cc+3)*LDA + r] = v.w;
    }
    __syncthreads();

    mlp_layer256<128, true>(A_T,  W1, b1, Bs, H1_T);
    __syncthreads();
    mlp_layer256<256, true>(H1_T, W2, b2, Bs, H2_T);
    __syncthreads();

    // ---- layer 3 inline (NOUTL=128, CW=4), epilogue fuses err for stage 6 ----
    {
        constexpr int NOUTL = 128, CW = 4;
        const int tx = tid & 7;
        const int ty = tid >> 3;
        unsigned long long acc[CW][4] = {};

        #pragma unroll 1
        for (int kh = 0; kh < 256; kh += KCH) {
            #pragma unroll
            for (int i = tid; i < KCH*NOUTL/4; i += 256) {
                int kr = i >> 5, c4 = (i & 31) << 2;
                float4 w = *(const float4*)(W3 + (size_t)(kh + kr)*NOUTL + c4);
                float* dst = Bs + ((kr << 7) + c4)*2;
                *(float4*)(dst)     = make_float4(w.x, w.x, w.y, w.y);
                *(float4*)(dst + 4) = make_float4(w.z, w.z, w.w, w.w);
            }
            __syncthreads();
            #pragma unroll
            for (int k = 0; k < KCH; ++k) {
                const float* arow = H2_T + (kh + k)*LDA + tx*8;
                ulonglong2 a01 = *(const ulonglong2*)arow;
                ulonglong2 a23 = *(const ulonglong2*)(arow + 4);
                unsigned long long av[4] = {a01.x, a01.y, a23.x, a23.y};
                const float* brow = Bs + ((k << 7) + ty*CW)*2;
                ulonglong2 b01 = *(const ulonglong2*)(brow);
                ulonglong2 b23 = *(const ulonglong2*)(brow + 4);
                #pragma unroll
                for (int r = 0; r < 4; ++r) {
                    fma2(acc[0][r], av[r], b01.x);
                    fma2(acc[1][r], av[r], b01.y);
                    fma2(acc[2][r], av[r], b23.x);
                    fma2(acc[3][r], av[r], b23.y);
                }
            }
            __syncthreads();
        }

        // epilogue: transpose microtile, add bias, write k_out
        float4 bb = *(const float4*)(b3 + ty*4);
        float o[8][4];
        #pragma unroll
        for (int c = 0; c < 4; ++c) {
            float bj = (c == 0) ? bb.x : (c == 1) ? bb.y : (c == 2) ? bb.z : bb.w;
            #pragma unroll
            for (int r = 0; r < 4; ++r) {
                float2 p = unpack2(acc[c][r]);
                o[2*r  ][c] = p.x + bj;
                o[2*r+1][c] = p.y + bj;
            }
        }
        #pragma unroll
        for (int r = 0; r < 8; ++r) {
            float4 v = {o[r][0], o[r][1], o[r][2], o[r][3]};
            *(float4*)(kout + (size_t)(row0 + tx*8 + r)*NS + ty*4) = v;
        }

        if (stage == 6) {
            // fused error-ratio accumulation: k7 in o[][], y1 in A_T
            const float* kc0 = g_k[k0s];
            const float* kc2 = g_k[2];
            const float* kc3 = g_k[3];
            const float* kc4 = g_k[4];
            const float* kc5 = g_k[5];
            #pragma unroll
            for (int r = 0; r < 8; ++r) {
                int lr = tx*8 + r;
                size_t gi = (size_t)(row0 + lr)*NS + ty*4;
                float4 k0v = *(const float4*)(kc0 + gi);
                float4 k2v = *(const float4*)(kc2 + gi);
                float4 k3v = *(const float4*)(kc3 + gi);
                float4 k4v = *(const float4*)(kc4 + gi);
                float4 k5v = *(const float4*)(kc5 + gi);
                float4 yv  = *(const float4*)(y + gi);
                float k0a[4] = {k0v.x, k0v.y, k0v.z, k0v.w};
                float k2a[4] = {k2v.x, k2v.y, k2v.z, k2v.w};
                float k3a[4] = {k3v.x, k3v.y, k3v.z, k3v.w};
                float k4a[4] = {k4v.x, k4v.y, k4v.z, k4v.w};
                float k5a[4] = {k5v.x, k5v.y, k5v.z, k5v.w};
                float ya[4]  = {yv.x, yv.y, yv.z, yv.w};
                #pragma unroll
                for (int c = 0; c < 4; ++c) {
                    float y1e = A_T[(ty*4 + c)*LDA + lr];
                    float e = c_errv[0]*k0a[c] + c_errv[2]*k2a[c]
                            + c_errv[3]*k3a[c] + c_errv[4]*k4a[c]
                            + c_errv[5]*k5a[c] + c_errv[6]*o[r][c];
                    e *= dt;
                    float tol = ATOLv + RTOLv * fmaxf(fabsf(ya[c]), fabsf(y1e));
                    float ratio = e / tol;
                    errloc += (double)ratio * (double)ratio;
                }
            }
        }
    }
}

// ---------------------------------------------------------------------------
// Reductions / controller (device-side, persistent kernel)
// ---------------------------------------------------------------------------
__device__ double block_reduce_d(double v, double* sh) {
    const int tid = threadIdx.x;
    sh[tid] = v;
    __syncthreads();
    #pragma unroll
    for (int s = 128; s > 0; s >>= 1) {
        if (tid < s) sh[tid] += sh[tid + s];
        __syncthreads();
    }
    double r = sh[0];
    __syncthreads();
    return r;
}

__device__ void ctrl_init_dev() {
    VC->sum0 = 0.0; VC->sum1 = 0.0; VC->sum2 = 0.0; VC->errsum = 0.0;
    VC->t = 0.f; VC->dt = 0.f; VC->dt_last = 0.f; VC->last_t = 0.f;
    VC->h0 = 0.f; VC->d1 = 0.f;
    VC->done = 0; VC->cur = 0; VC->k0slot = 0;
}

__device__ void ctrl_h0_dev() {
    float d0 = (float)sqrt(VC->sum0);
    float d1 = (float)sqrt(VC->sum1);
    float h0 = (d0 < 1e-5f || d1 < 1e-5f) ? 1e-6f : 0.01f * d0 / d1;
    VC->h0 = h0;
    VC->d1 = d1;
}

__device__ void ctrl_dt0_dev() {
    float h0 = VC->h0;
    float d1 = VC->d1;
    float d2 = (float)sqrt(VC->sum2) / h0;
    float h1;
    if (d1 <= 1e-15f && d2 <= 1e-15f)
        h1 = fmaxf(1e-6f, h0 * 1e-3f);
    else
        h1 = powf(0.01f / fmaxf(d1, d2), 0.2f);
    VC->dt = fminf(100.f * h0, h1);
    VC->t = 0.f;
    VC->last_t = 0.f;
    VC->errsum = 0.0;
}

__device__ void ctrl_update_dev() {
    float err = (float)sqrt(VC->errsum / (double)NEL);
    float dfac = (err < 1.f) ? 1.f : 0.2f;
    float factor = fminf(10.f, fmaxf(powf(err, -0.2f) * 0.9f, dfac));
    float dtcur = VC->dt;
    float dtnew = (err == 0.f) ? dtcur * 10.f : dtcur * factor;
    dtnew = fmaxf(dtnew, 0.f);
    if (err <= 1.f) {               // accept
        VC->last_t = VC->t;
        VC->t      = VC->t + dtcur;
        VC->dt_last = dtcur;
        VC->cur    = VC->cur ^ 1;
        VC->k0slot = VC->k0slot ^ 6;   // FSAL
        if (VC->t >= 1.0f) VC->done = 1;
    }
    VC->dt = dtnew;
    VC->errsum = 0.0;
}

// ---------------------------------------------------------------------------
// The persistent kernel: whole adaptive dopri5 integration in one launch
// ---------------------------------------------------------------------------
__global__ void __launch_bounds__(256, 1)
ode_persistent(const float* __restrict__ x,
               const float* __restrict__ W1, const float* __restrict__ b1,
               const float* __restrict__ W2, const float* __restrict__ b2,
               const float* __restrict__ W3, const float* __restrict__ b3)
{
    extern __shared__ float sm[];
    double* shred = (double*)sm;     // 256 doubles overlay for block reduce
    const int tid = threadIdx.x;
    const int bid = blockIdx.x;

    if (bid == 0 && tid == 0) ctrl_init_dev();

    // y0 = [x | zeros]
    for (int tile = bid; tile < NTILES; tile += NBLOCKS)
        for (int i = tid; i < ROWS_PB*NS; i += 256) {
            int r = i >> 7, cc = i & 127;
            size_t row = (size_t)tile*ROWS_PB + r;
            g_ybuf[0][row*NS + cc] = (cc < DIN) ? x[row*DIN + cc] : 0.f;
        }
    grid_barrier();

    // f0 = f(y0) -> slot 0
    double dummy = 0.0;
    for (int tile = bid; tile < NTILES; tile += NBLOCKS) {
        tile_stage(-1, tile, 0, 0, 0.f, 0.f, W1, b1, W2, b2, W3, b3, sm, dummy);
        __syncthreads();
    }
    // d0/d1 norms
    {
        double s0 = 0.0, s1 = 0.0;
        const float4* y4 = (const float4*)g_ybuf[0];
        const float4* f4 = (const float4*)g_k[0];
        for (int tile = bid; tile < NTILES; tile += NBLOCKS) {
            size_t b4 = (size_t)tile*ROWS_PB*NS/4;
            for (int i = tid; i < ROWS_PB*NS/4; i += 256) {
                float4 y0 = y4[b4 + i];
                float4 f0 = f4[b4 + i];
                float sc, a, b;
                sc = ATOLv + RTOLv*fabsf(y0.x); a = y0.x/sc; b = f0.x/sc;
                s0 += (double)a*a; s1 += (double)b*b;
                sc = ATOLv + RTOLv*fabsf(y0.y); a = y0.y/sc; b = f0.y/sc;
                s0 += (double)a*a; s1 += (double)b*b;
                sc = ATOLv + RTOLv*fabsf(y0.z); a = y0.z/sc; b = f0.z/sc;
                s0 += (double)a*a; s1 += (double)b*b;
                sc = ATOLv + RTOLv*fabsf(y0.w); a = y0.w/sc; b = f0.w/sc;
                s0 += (double)a*a; s1 += (double)b*b;
            }
        }
        double r0 = block_reduce_d(s0, shred);
        double r1 = block_reduce_d(s1, shred);
        if (tid == 0) {
            atomicAdd(&g_ctrl.sum0, r0);
            atomicAdd(&g_ctrl.sum1, r1);
        }
    }
    grid_barrier();
    if (bid == 0 && tid == 0) ctrl_h0_dev();
    grid_barrier();

    // probe f(y0 + h0*f0) -> slot 1
    {
        float h0 = VC->h0;
        for (int tile = bid; tile < NTILES; tile += NBLOCKS) {
            tile_stage(-2, tile, 0, 0, 0.f, h0, W1, b1, W2, b2, W3, b3, sm, dummy);
            __syncthreads();
        }
        double s2 = 0.0;
        const float4* y4 = (const float4*)g_ybuf[0];
        const float4* k04 = (const float4*)g_k[0];
        const float4* k14 = (const float4*)g_k[1];
        for (int tile = bid; tile < NTILES; tile += NBLOCKS) {
            size_t b4 = (size_t)tile*ROWS_PB*NS/4;
            for (int i = tid; i < ROWS_PB*NS/4; i += 256) {
                float4 y0 = y4[b4 + i];
                float4 k0 = k04[b4 + i];
                float4 k1 = k14[b4 + i];
                float sc, d;
                sc = ATOLv + RTOLv*fabsf(y0.x); d = (k1.x - k0.x)/sc; s2 += (double)d*d;
                sc = ATOLv + RTOLv*fabsf(y0.y); d = (k1.y - k0.y)/sc; s2 += (double)d*d;
                sc = ATOLv + RTOLv*fabsf(y0.z); d = (k1.z - k0.z)/sc; s2 += (double)d*d;
                sc = ATOLv + RTOLv*fabsf(y0.w); d = (k1.w - k0.w)/sc; s2 += (double)d*d;
            }
        }
        double r2 = block_reduce_d(s2, shred);
        if (tid == 0) atomicAdd(&g_ctrl.sum2, r2);
    }
    grid_barrier();
    if (bid == 0 && tid == 0) ctrl_dt0_dev();
    grid_barrier();

    // adaptive dopri5 attempts — device-side while loop, breaks when done
    for (int it = 0; it < MAXIT; ++it) {
        if (VC->done) break;
        float dt = VC->dt;
        int cur  = VC->cur;
        int k0s  = VC->k0slot;

        double eloc = 0.0;
        for (int tile = bid; tile < NTILES; tile += NBLOCKS) {
            #pragma unroll 1
            for (int s = 1; s <= 6; ++s) {
                tile_stage(s, tile, cur, k0s, dt, 0.f,
                           W1, b1, W2, b2, W3, b3, sm, eloc);
                __syncthreads();
            }
        }
        double rsum = block_reduce_d(eloc, shred);
        if (tid == 0) atomicAdd(&g_ctrl.errsum, rsum);
        grid_barrier();
        if (bid == 0 && tid == 0) ctrl_update_dev();
        grid_barrier();
    }
}

// ---------------------------------------------------------------------------
// Final: 4th-order interpolation at t=1, then linear layer @ Wl + bl
// ---------------------------------------------------------------------------
__global__ void __launch_bounds__(256)
final_kernel(const float* __restrict__ Wl, const float* __restrict__ bl,
             float* __restrict__ out)
{
    __shared__ float yt_s[64*132];
    __shared__ float wl_s[128*NOUTC];
    __shared__ float bl_s[NOUTC];

    const int tid = threadIdx.x;
    const int row0 = blockIdx.x * 64;

    for (int i = tid; i < 128*NOUTC; i += 256) wl_s[i] = Wl[i];
    if (tid < NOUTC) bl_s[tid] = bl[tid];

    const int cur = g_ctrl.cur;
    const int k0s = g_ctrl.k0slot;
    const float dtl = g_ctrl.dt_last;
    const float s  = (1.0f - g_ctrl.last_t) / (g_ctrl.t - g_ctrl.last_t);
    const float* yprev = g_ybuf[cur ^ 1];
    const float* ycur  = g_ybuf[cur];
    const float* k0p = g_k[k0s ^ 6];   // accepted step's k1 (pre-flip slot)
    const float* k6p = g_k[k0s];       // accepted step's k7

    for (int i = tid; i < 64*NS; i += 256) {
        int r = i >> 7, cc = i & 127;
        size_t g = (size_t)(row0 + r)*NS + cc;
        float y0e = yprev[g];
        float y1e = ycur[g];
        float k0v = k0p[g], k6v = k6p[g];
        float kmid = c_midv[0]*k0v + c_midv[2]*g_k[2][g] + c_midv[3]*g_k[3][g]
                   + c_midv[4]*g_k[4][g] + c_midv[5]*g_k[5][g] + c_midv[6]*k6v;
        float ymid = y0e + dtl * kmid;
        float dy0 = dtl * k0v, dy1 = dtl * k6v;
        float a = -2.f*dy0 + 2.f*dy1 -  8.f*y0e -  8.f*y1e + 16.f*ymid;
        float b =  5.f*dy0 - 3.f*dy1 + 18.f*y0e + 14.f*y1e - 32.f*ymid;
        float c = -4.f*dy0 +     dy1 - 11.f*y0e -  5.f*y1e + 16.f*ymid;
        float d = dy0;
        float e = y0e;
        yt_s[r*132 + cc] = (((a*s + b)*s + c)*s + d)*s + e;
    }
    __syncthreads();

    for (int idx = tid; idx < 64*NOUTC; idx += 256) {
        int r = idx / NOUTC, c = idx % NOUTC;
        float acc = bl_s[c];
        const float* yr = yt_s + r*132;
        #pragma unroll 8
        for (int kk = 0; kk < NS; ++kk)
            acc = fmaf(yr[kk], wl_s[kk*NOUTC + c], acc);
        out[(size_t)(row0 + r)*NOUTC + c] = acc;
    }
}

// ---------------------------------------------------------------------------
// Launch: 2 kernels total, fully graph-capturable
// ---------------------------------------------------------------------------
extern "C" void kernel_launch(void* const* d_in, const int* in_sizes, int n_in,
                              void* d_out, int out_size)
{
    const float* x  = (const float*)d_in[0];
    const float* W1 = (const float*)d_in[1];
    const float* b1 = (const float*)d_in[2];
    const float* W2 = (const float*)d_in[3];
    const float* b2 = (const float*)d_in[4];
    const float* W3 = (const float*)d_in[5];
    const float* b3 = (const float*)d_in[6];
    const float* Wl = (const float*)d_in[7];
    const float* bl = (const float*)d_in[8];
    float* out = (float*)d_out;

    cudaFuncSetAttribute(ode_persistent,
                         cudaFuncAttributeMaxDynamicSharedMemorySize, SMEM_BYTES);

    ode_persistent<<<NBLOCKS, 256, SMEM_BYTES>>>(x, W1, b1, W2, b2, W3, b3);
    final_kernel<<<NTILES, 256>>>(Wl, bl, out);
}

// round 6
// speedup vs baseline: 1.2543x; 1.2543x over previous
#include <cuda_runtime.h>
#include <math.h>
#include <stdint.h>

// ---------------------------------------------------------------------------
// Problem constants
// ---------------------------------------------------------------------------
#define BATCH   65536
#define DIN     118
#define NS      128          // ODE state dim (118 + 10 aug)
#define NH      256          // hidden dim
#define NOUTC   10           // output dim
#define NEL     (BATCH*NS)   // 8388608 state elements
#define ROWS_PB 64           // batch rows per tile
#define NTILES  (BATCH/ROWS_PB)   // 1024 tiles
#define NBLOCKS 148          // persistent blocks, 1 per SM
#define MAXIT   20           // attempt safety bound (loop breaks on done)
#define RTOLv   1e-3f
#define ATOLv   1e-3f
#define LDA     68           // smem K-major row stride (64 rows + 4 pad)
#define KCH     32           // K chunk staged through smem (round-4 proven)

// smem: A_T[128][LDA] + H1_T[256][LDA] + H2_T[256][LDA] + Bs[KCH][256]
#define SMEM_FLOATS (128*LDA + 256*LDA + 256*LDA + KCH*256)
#define SMEM_BYTES  (SMEM_FLOATS*4)

// ---------------------------------------------------------------------------
// Device global scratch
// ---------------------------------------------------------------------------
__device__ float g_ybuf[2][NEL];   // double-buffered state y
__device__ float g_k[7][NEL];      // RK stages; slots {0,6} swap as k1/k7 (FSAL)

struct Ctrl {
    double sum0, sum1, sum2, errsum;
    float  t, dt, dt_last, last_t, h0, d1;
    int    done, cur, k0slot;
};
__device__ Ctrl g_ctrl;
#define VC ((volatile Ctrl*)&g_ctrl)

// grid barrier (sense-reversal via phase counter)
__device__ unsigned g_bar_count = 0;
__device__ volatile unsigned g_bar_phase = 0;

__device__ __forceinline__ void grid_barrier() {
    __syncthreads();
    if (threadIdx.x == 0) {
        unsigned ph = g_bar_phase;
        __threadfence();
        if (atomicAdd(&g_bar_count, 1u) == NBLOCKS - 1) {
            g_bar_count = 0;
            __threadfence();
            g_bar_phase = ph + 1;
        } else {
            while (g_bar_phase == ph) { }
        }
        __threadfence();
    }
    __syncthreads();
}

// ---------------------------------------------------------------------------
// Dopri5 tableau (exactly as jax.experimental.ode, double -> float)
// ---------------------------------------------------------------------------
__constant__ float c_beta[6][6] = {
    {(float)(1.0/5.0), 0.f, 0.f, 0.f, 0.f, 0.f},
    {(float)(3.0/40.0), (float)(9.0/40.0), 0.f, 0.f, 0.f, 0.f},
    {(float)(44.0/45.0), (float)(-56.0/15.0), (float)(32.0/9.0), 0.f, 0.f, 0.f},
    {(float)(19372.0/6561.0), (float)(-25360.0/2187.0), (float)(64448.0/6561.0),
     (float)(-212.0/729.0), 0.f, 0.f},
    {(float)(9017.0/3168.0), (float)(-355.0/33.0), (float)(46732.0/5247.0),
     (float)(49.0/176.0), (float)(-5103.0/18656.0), 0.f},
    {(float)(35.0/384.0), 0.f, (float)(500.0/1113.0), (float)(125.0/192.0),
     (float)(-2187.0/6784.0), (float)(11.0/84.0)}
};
__constant__ float c_errv[7] = {
    (float)(35.0/384.0 - 1951.0/21600.0), 0.f,
    (float)(500.0/1113.0 - 22642.0/50085.0),
    (float)(125.0/192.0 - 451.0/720.0),
    (float)(-2187.0/6784.0 + 12231.0/42400.0),
    (float)(11.0/84.0 - 649.0/6300.0),
    (float)(-1.0/60.0)
};
__constant__ float c_midv[7] = {
    (float)(6025192743.0/30085553152.0/2.0), 0.f,
    (float)(51252292925.0/65400821598.0/2.0),
    (float)(-2691868925.0/45128329728.0/2.0),
    (float)(187940372067.0/1594534317056.0/2.0),
    (float)(-1776094331.0/19743644256.0/2.0),
    (float)(11237099.0/235043384.0/2.0)
};

// ---------------------------------------------------------------------------
// f32x2 packed-FMA helpers
// ---------------------------------------------------------------------------
__device__ __forceinline__ void fma2(unsigned long long &d,
                                     unsigned long long a,
                                     unsigned long long b) {
    asm("fma.rn.f32x2 %0, %1, %2, %0;" : "+l"(d) : "l"(a), "l"(b));
}
__device__ __forceinline__ unsigned long long dup2(float b) {
    unsigned long long r;
    asm("mov.b64 %0, {%1, %1};" : "=l"(r) : "f"(b));
    return r;
}
__device__ __forceinline__ float2 unpack2(unsigned long long v) {
    float2 r;
    asm("mov.b64 {%0, %1}, %2;" : "=f"(r.x), "=f"(r.y) : "l"(v));
    return r;
}

// ---------------------------------------------------------------------------
// Layer with NOUTL=256 output cols (layers 1 and 2) — round-4 proven form.
// Thread map: tx = tid&7 -> 8-row group, ty = tid>>3 -> 8-col group.
// ---------------------------------------------------------------------------
template<int KD, bool RELU>
__device__ __forceinline__ void mlp_layer256(
    const float* __restrict__ At,    // smem [KD][LDA] K-major
    const float* __restrict__ Wg,    // global [KD][256] row-major
    const float* __restrict__ bias,
    float* __restrict__ Bs,          // smem staging [KCH][256]
    float* __restrict__ OutT)        // smem K-major out [256][LDA]
{
    constexpr int NOUTL = 256, CW = 8;
    const int tid = threadIdx.x;
    const int tx  = tid & 7;
    const int ty  = tid >> 3;

    unsigned long long acc[CW][4] = {};

    #pragma unroll
    for (int kh = 0; kh < KD; kh += KCH) {
        // stage W chunk [KCH][256] into smem (coalesced float4)
        #pragma unroll
        for (int i = tid; i < KCH*NOUTL/4; i += 256) {
            int kr = i >> 6, c4 = (i & 63) << 2;
            *(float4*)(Bs + (kr << 8) + c4) =
                *(const float4*)(Wg + (size_t)(kh + kr)*NOUTL + c4);
        }
        __syncthreads();

        #pragma unroll 2
        for (int k = 0; k < KCH; ++k) {
            const float* arow = At + (kh + k)*LDA + tx*8;
            ulonglong2 a01 = *(const ulonglong2*)arow;
            ulonglong2 a23 = *(const ulonglong2*)(arow + 4);
            unsigned long long av[4] = {a01.x, a01.y, a23.x, a23.y};

            const float* brow = Bs + (k << 8) + ty*CW;
            float bv[8];
            *(float4*)bv       = *(const float4*)brow;
            *(float4*)(bv + 4) = *(const float4*)(brow + 4);

            #pragma unroll
            for (int c = 0; c < CW; ++c) {
                unsigned long long bd = dup2(bv[c]);
                #pragma unroll
                for (int r = 0; r < 4; ++r)
                    fma2(acc[c][r], av[r], bd);
            }
        }
        __syncthreads();
    }

    #pragma unroll
    for (int c = 0; c < CW; ++c) {
        int col = ty*CW + c;
        float bj = bias[col];
        float2 p0 = unpack2(acc[c][0]);
        float2 p1 = unpack2(acc[c][1]);
        float2 p2 = unpack2(acc[c][2]);
        float2 p3 = unpack2(acc[c][3]);
        float4 v0 = {p0.x + bj, p0.y + bj, p1.x + bj, p1.y + bj};
        float4 v1 = {p2.x + bj, p2.y + bj, p3.x + bj, p3.y + bj};
        if (RELU) {
            v0.x = fmaxf(v0.x, 0.f); v0.y = fmaxf(v0.y, 0.f);
            v0.z = fmaxf(v0.z, 0.f); v0.w = fmaxf(v0.w, 0.f);
            v1.x = fmaxf(v1.x, 0.f); v1.y = fmaxf(v1.y, 0.f);
            v1.z = fmaxf(v1.z, 0.f); v1.w = fmaxf(v1.w, 0.f);
        }
        *(float4*)(OutT + col*LDA + tx*8)     = v0;
        *(float4*)(OutT + col*LDA + tx*8 + 4) = v1;
    }
}

// ---------------------------------------------------------------------------
// Full stage for one 64-row tile. Stage 6 also writes y1 and accumulates
// the per-element error ratio (fused err_reduce).
//  stage = -1 : f0 eval (yi = y)
//  stage = -2 : init probe (yi = y + h0*f0) -> slot 1
//  stage = 1..6 : dopri stages
// ---------------------------------------------------------------------------
__device__ void tile_stage(
    int stage, int tile, int cur, int k0s, float dt, float h0,
    const float* __restrict__ W1, const float* __restrict__ b1,
    const float* __restrict__ W2, const float* __restrict__ b2,
    const float* __restrict__ W3, const float* __restrict__ b3,
    float* sm, double& errloc)
{
    float* A_T  = sm;                       // [128][LDA]  (holds y1 for stage 6)
    float* H1_T = sm + 128*LDA;             // [256][LDA]
    float* H2_T = H1_T + 256*LDA;           // [256][LDA]
    float* Bs   = H2_T + 256*LDA;           // [KCH][256]

    const int tid  = threadIdx.x;
    const int row0 = tile * ROWS_PB;
    const float* y = g_ybuf[cur];
    float* ynext   = g_ybuf[cur ^ 1];

    const float* kparr[6];
    kparr[0] = g_k[k0s];
    kparr[1] = g_k[1]; kparr[2] = g_k[2]; kparr[3] = g_k[3];
    kparr[4] = g_k[4]; kparr[5] = g_k[5];

    float coef[6];
    int nk, outslot;
    if (stage == -1)      { nk = 0; outslot = k0s; }
    else if (stage == -2) { nk = 1; coef[0] = h0; outslot = 1; }
    else {
        nk = stage;
        #pragma unroll
        for (int j = 0; j < 6; ++j) coef[j] = dt * c_beta[stage-1][j];
        outslot = (stage < 6) ? stage : (k0s ^ 6);
    }
    float* kout = g_k[outslot];

    // phase 0: stage input -> A_T (K-major); stage 6 also emits y1
    for (int i = tid; i < ROWS_PB*NS/4; i += 256) {
        int r  = i >> 5;
        int c4 = i & 31;
        size_t g4 = ((size_t)(row0 + r)*NS >> 2) + c4;
        float4 v = ((const float4*)y)[g4];
        for (int j = 0; j < nk; ++j) {
            float4 kv = ((const float4*)kparr[j])[g4];
            v.x = fmaf(coef[j], kv.x, v.x);
            v.y = fmaf(coef[j], kv.y, v.y);
            v.z = fmaf(coef[j], kv.z, v.z);
            v.w = fmaf(coef[j], kv.w, v.w);
        }
        if (stage == 6) ((float4*)ynext)[g4] = v;
        int cc = c4 * 4;
        A_T[(cc+0)*LDA + r] = v.x;
        A_T[(cc+1)*LDA + r] = v.y;
        A_T[(cc+2)*LDA + r] = v.z;
        A_T[(cc+3)*LDA + r] = v.w;
    }
    __syncthreads();

    mlp_layer256<128, true>(A_T,  W1, b1, Bs, H1_T);
    __syncthreads();
    mlp_layer256<256, true>(H1_T, W2, b2, Bs, H2_T);
    __syncthreads();

    // ---- layer 3 (NOUTL=128, CW=4), round-4 form; stage-6 fuses err ----
    {
        constexpr int NOUTL = 128, CW = 4;
        const int tx = tid & 7;
        const int ty = tid >> 3;
        unsigned long long acc[CW][4] = {};

        #pragma unroll
        for (int kh = 0; kh < 256; kh += KCH) {
            #pragma unroll
            for (int i = tid; i < KCH*NOUTL/4; i += 256) {
                int kr = i >> 5, c4 = (i & 31) << 2;
                *(float4*)(Bs + (kr << 7) + c4) =
                    *(const float4*)(W3 + (size_t)(kh + kr)*NOUTL + c4);
            }
            __syncthreads();
            #pragma unroll 2
            for (int k = 0; k < KCH; ++k) {
                const float* arow = H2_T + (kh + k)*LDA + tx*8;
                ulonglong2 a01 = *(const ulonglong2*)arow;
                ulonglong2 a23 = *(const ulonglong2*)(arow + 4);
                unsigned long long av[4] = {a01.x, a01.y, a23.x, a23.y};
                const float* brow = Bs + (k << 7) + ty*CW;
                float bv[4];
                *(float4*)bv = *(const float4*)brow;
                #pragma unroll
                for (int c = 0; c < CW; ++c) {
                    unsigned long long bd = dup2(bv[c]);
                    #pragma unroll
                    for (int r = 0; r < 4; ++r)
                        fma2(acc[c][r], av[r], bd);
                }
            }
            __syncthreads();
        }

        // epilogue: transpose microtile, add bias, write k_out
        float4 bb = *(const float4*)(b3 + ty*4);
        float o[8][4];
        #pragma unroll
        for (int c = 0; c < 4; ++c) {
            float bj = (c == 0) ? bb.x : (c == 1) ? bb.y : (c == 2) ? bb.z : bb.w;
            #pragma unroll
            for (int r = 0; r < 4; ++r) {
                float2 p = unpack2(acc[c][r]);
                o[2*r  ][c] = p.x + bj;
                o[2*r+1][c] = p.y + bj;
            }
        }
        #pragma unroll
        for (int r = 0; r < 8; ++r) {
            float4 v = {o[r][0], o[r][1], o[r][2], o[r][3]};
            *(float4*)(kout + (size_t)(row0 + tx*8 + r)*NS + ty*4) = v;
        }

        if (stage == 6) {
            // fused error-ratio accumulation: k7 in o[][], y1 in A_T
            const float* kc0 = g_k[k0s];
            const float* kc2 = g_k[2];
            const float* kc3 = g_k[3];
            const float* kc4 = g_k[4];
            const float* kc5 = g_k[5];
            #pragma unroll
            for (int r = 0; r < 8; ++r) {
                int lr = tx*8 + r;
                size_t gi = (size_t)(row0 + lr)*NS + ty*4;
                float4 k0v = *(const float4*)(kc0 + gi);
                float4 k2v = *(const float4*)(kc2 + gi);
                float4 k3v = *(const float4*)(kc3 + gi);
                float4 k4v = *(const float4*)(kc4 + gi);
                float4 k5v = *(const float4*)(kc5 + gi);
                float4 yv  = *(const float4*)(y + gi);
                float k0a[4] = {k0v.x, k0v.y, k0v.z, k0v.w};
                float k2a[4] = {k2v.x, k2v.y, k2v.z, k2v.w};
                float k3a[4] = {k3v.x, k3v.y, k3v.z, k3v.w};
                float k4a[4] = {k4v.x, k4v.y, k4v.z, k4v.w};
                float k5a[4] = {k5v.x, k5v.y, k5v.z, k5v.w};
                float ya[4]  = {yv.x, yv.y, yv.z, yv.w};
                #pragma unroll
                for (int c = 0; c < 4; ++c) {
                    float y1e = A_T[(ty*4 + c)*LDA + lr];
                    float e = c_errv[0]*k0a[c] + c_errv[2]*k2a[c]
                            + c_errv[3]*k3a[c] + c_errv[4]*k4a[c]
                            + c_errv[5]*k5a[c] + c_errv[6]*o[r][c];
                    e *= dt;
                    float tol = ATOLv + RTOLv * fmaxf(fabsf(ya[c]), fabsf(y1e));
                    float ratio = e / tol;
                    errloc += (double)ratio * (double)ratio;
                }
            }
        }
    }
}

// ---------------------------------------------------------------------------
// Reductions / controller (device-side)
// ---------------------------------------------------------------------------
__device__ double block_reduce_d(double v, double* sh) {
    const int tid = threadIdx.x;
    sh[tid] = v;
    __syncthreads();
    #pragma unroll
    for (int s = 128; s > 0; s >>= 1) {
        if (tid < s) sh[tid] += sh[tid + s];
        __syncthreads();
    }
    double r = sh[0];
    __syncthreads();
    return r;
}

__device__ void ctrl_init_dev() {
    VC->sum0 = 0.0; VC->sum1 = 0.0; VC->sum2 = 0.0; VC->errsum = 0.0;
    VC->t = 0.f; VC->dt = 0.f; VC->dt_last = 0.f; VC->last_t = 0.f;
    VC->h0 = 0.f; VC->d1 = 0.f;
    VC->done = 0; VC->cur = 0; VC->k0slot = 0;
}

__device__ void ctrl_h0_dev() {
    float d0 = (float)sqrt(VC->sum0);
    float d1 = (float)sqrt(VC->sum1);
    float h0 = (d0 < 1e-5f || d1 < 1e-5f) ? 1e-6f : 0.01f * d0 / d1;
    VC->h0 = h0;
    VC->d1 = d1;
}

__device__ void ctrl_dt0_dev() {
    float h0 = VC->h0;
    float d1 = VC->d1;
    float d2 = (float)sqrt(VC->sum2) / h0;
    float h1;
    if (d1 <= 1e-15f && d2 <= 1e-15f)
        h1 = fmaxf(1e-6f, h0 * 1e-3f);
    else
        h1 = powf(0.01f / fmaxf(d1, d2), 0.2f);
    VC->dt = fminf(100.f * h0, h1);
    VC->t = 0.f;
    VC->last_t = 0.f;
    VC->errsum = 0.0;
}

__device__ void ctrl_update_dev() {
    float err = (float)sqrt(VC->errsum / (double)NEL);
    float dfac = (err < 1.f) ? 1.f : 0.2f;
    float factor = fminf(10.f, fmaxf(powf(err, -0.2f) * 0.9f, dfac));
    float dtcur = VC->dt;
    float dtnew = (err == 0.f) ? dtcur * 10.f : dtcur * factor;
    dtnew = fmaxf(dtnew, 0.f);
    if (err <= 1.f) {               // accept
        VC->last_t = VC->t;
        VC->t      = VC->t + dtcur;
        VC->dt_last = dtcur;
        VC->cur    = VC->cur ^ 1;
        VC->k0slot = VC->k0slot ^ 6;   // FSAL
        if (VC->t >= 1.0f) VC->done = 1;
    }
    VC->dt = dtnew;
    VC->errsum = 0.0;
}

// ---------------------------------------------------------------------------
// Persistent kernel: whole adaptive dopri5 integration in one launch
// ---------------------------------------------------------------------------
__global__ void __launch_bounds__(256, 1)
ode_persistent(const float* __restrict__ x,
               const float* __restrict__ W1, const float* __restrict__ b1,
               const float* __restrict__ W2, const float* __restrict__ b2,
               const float* __restrict__ W3, const float* __restrict__ b3)
{
    extern __shared__ float sm[];
    double* shred = (double*)sm;     // 256-double overlay for block reduce
    const int tid = threadIdx.x;
    const int bid = blockIdx.x;

    if (bid == 0 && tid == 0) ctrl_init_dev();

    // y0 = [x | zeros]
    for (int tile = bid; tile < NTILES; tile += NBLOCKS)
        for (int i = tid; i < ROWS_PB*NS; i += 256) {
            int r = i >> 7, cc = i & 127;
            size_t row = (size_t)tile*ROWS_PB + r;
            g_ybuf[0][row*NS + cc] = (cc < DIN) ? x[row*DIN + cc] : 0.f;
        }
    grid_barrier();

    // f0 = f(y0) -> slot 0
    double dummy = 0.0;
    for (int tile = bid; tile < NTILES; tile += NBLOCKS) {
        tile_stage(-1, tile, 0, 0, 0.f, 0.f, W1, b1, W2, b2, W3, b3, sm, dummy);
        __syncthreads();
    }
    // d0/d1 norms
    {
        double s0 = 0.0, s1 = 0.0;
        const float4* y4 = (const float4*)g_ybuf[0];
        const float4* f4 = (const float4*)g_k[0];
        for (int tile = bid; tile < NTILES; tile += NBLOCKS) {
            size_t b4 = (size_t)tile*ROWS_PB*NS/4;
            for (int i = tid; i < ROWS_PB*NS/4; i += 256) {
                float4 y0 = y4[b4 + i];
                float4 f0 = f4[b4 + i];
                float sc, a, b;
                sc = ATOLv + RTOLv*fabsf(y0.x); a = y0.x/sc; b = f0.x/sc;
                s0 += (double)a*a; s1 += (double)b*b;
                sc = ATOLv + RTOLv*fabsf(y0.y); a = y0.y/sc; b = f0.y/sc;
                s0 += (double)a*a; s1 += (double)b*b;
                sc = ATOLv + RTOLv*fabsf(y0.z); a = y0.z/sc; b = f0.z/sc;
                s0 += (double)a*a; s1 += (double)b*b;
                sc = ATOLv + RTOLv*fabsf(y0.w); a = y0.w/sc; b = f0.w/sc;
                s0 += (double)a*a; s1 += (double)b*b;
            }
        }
        double r0 = block_reduce_d(s0, shred);
        double r1 = block_reduce_d(s1, shred);
        if (tid == 0) {
            atomicAdd(&g_ctrl.sum0, r0);
            atomicAdd(&g_ctrl.sum1, r1);
        }
    }
    grid_barrier();
    if (bid == 0 && tid == 0) ctrl_h0_dev();
    grid_barrier();

    // probe f(y0 + h0*f0) -> slot 1
    {
        float h0 = VC->h0;
        for (int tile = bid; tile < NTILES; tile += NBLOCKS) {
            tile_stage(-2, tile, 0, 0, 0.f, h0, W1, b1, W2, b2, W3, b3, sm, dummy);
            __syncthreads();
        }
        double s2 = 0.0;
        const float4* y4 = (const float4*)g_ybuf[0];
        const float4* k04 = (const float4*)g_k[0];
        const float4* k14 = (const float4*)g_k[1];
        for (int tile = bid; tile < NTILES; tile += NBLOCKS) {
            size_t b4 = (size_t)tile*ROWS_PB*NS/4;
            for (int i = tid; i < ROWS_PB*NS/4; i += 256) {
                float4 y0 = y4[b4 + i];
                float4 k0 = k04[b4 + i];
                float4 k1 = k14[b4 + i];
                float sc, d;
                sc = ATOLv + RTOLv*fabsf(y0.x); d = (k1.x - k0.x)/sc; s2 += (double)d*d;
                sc = ATOLv + RTOLv*fabsf(y0.y); d = (k1.y - k0.y)/sc; s2 += (double)d*d;
                sc = ATOLv + RTOLv*fabsf(y0.z); d = (k1.z - k0.z)/sc; s2 += (double)d*d;
                sc = ATOLv + RTOLv*fabsf(y0.w); d = (k1.w - k0.w)/sc; s2 += (double)d*d;
            }
        }
        double r2 = block_reduce_d(s2, shred);
        if (tid == 0) atomicAdd(&g_ctrl.sum2, r2);
    }
    grid_barrier();
    if (bid == 0 && tid == 0) ctrl_dt0_dev();
    grid_barrier();

    // adaptive dopri5 attempts
    for (int it = 0; it < MAXIT; ++it) {
        if (VC->done) break;
        float dt = VC->dt;
        int cur  = VC->cur;
        int k0s  = VC->k0slot;

        double eloc = 0.0;
        for (int tile = bid; tile < NTILES; tile += NBLOCKS) {
            #pragma unroll 1
            for (int s = 1; s <= 6; ++s) {
                tile_stage(s, tile, cur, k0s, dt, 0.f,
                           W1, b1, W2, b2, W3, b3, sm, eloc);
                __syncthreads();
            }
        }
        double rsum = block_reduce_d(eloc, shred);
        if (tid == 0) atomicAdd(&g_ctrl.errsum, rsum);
        grid_barrier();
        if (bid == 0 && tid == 0) ctrl_update_dev();
        grid_barrier();
    }
}

// ---------------------------------------------------------------------------
// Final: 4th-order interpolation at t=1, then linear layer @ Wl + bl
// ---------------------------------------------------------------------------
__global__ void __launch_bounds__(256)
final_kernel(const float* __restrict__ Wl, const float* __restrict__ bl,
             float* __restrict__ out)
{
    __shared__ float yt_s[64*132];
    __shared__ float wl_s[128*NOUTC];
    __shared__ float bl_s[NOUTC];

    const int tid = threadIdx.x;
    const int row0 = blockIdx.x * 64;

    for (int i = tid; i < 128*NOUTC; i += 256) wl_s[i] = Wl[i];
    if (tid < NOUTC) bl_s[tid] = bl[tid];

    const int cur = g_ctrl.cur;
    const int k0s = g_ctrl.k0slot;
    const float dtl = g_ctrl.dt_last;
    const float s  = (1.0f - g_ctrl.last_t) / (g_ctrl.t - g_ctrl.last_t);
    const float* yprev = g_ybuf[cur ^ 1];
    const float* ycur  = g_ybuf[cur];
    const float* k0p = g_k[k0s ^ 6];   // accepted step's k1 (pre-flip slot)
    const float* k6p = g_k[k0s];       // accepted step's k7

    for (int i = tid; i < 64*NS; i += 256) {
        int r = i >> 7, cc = i & 127;
        size_t g = (size_t)(row0 + r)*NS + cc;
        float y0e = yprev[g];
        float y1e = ycur[g];
        float k0v = k0p[g], k6v = k6p[g];
        float kmid = c_midv[0]*k0v + c_midv[2]*g_k[2][g] + c_midv[3]*g_k[3][g]
                   + c_midv[4]*g_k[4][g] + c_midv[5]*g_k[5][g] + c_midv[6]*k6v;
        float ymid = y0e + dtl * kmid;
        float dy0 = dtl * k0v, dy1 = dtl * k6v;
        float a = -2.f*dy0 + 2.f*dy1 -  8.f*y0e -  8.f*y1e + 16.f*ymid;
        float b =  5.f*dy0 - 3.f*dy1 + 18.f*y0e + 14.f*y1e - 32.f*ymid;
        float c = -4.f*dy0 +     dy1 - 11.f*y0e -  5.f*y1e + 16.f*ymid;
        float d = dy0;
        float e = y0e;
        yt_s[r*132 + cc] = (((a*s + b)*s + c)*s + d)*s + e;
    }
    __syncthreads();

    for (int idx = tid; idx < 64*NOUTC; idx += 256) {
        int r = idx / NOUTC, c = idx % NOUTC;
        float acc = bl_s[c];
        const float* yr = yt_s + r*132;
        #pragma unroll 8
        for (int kk = 0; kk < NS; ++kk)
            acc = fmaf(yr[kk], wl_s[kk*NOUTC + c], acc);
        out[(size_t)(row0 + r)*NOUTC + c] = acc;
    }
}

// ---------------------------------------------------------------------------
// Launch: 2 kernels total, fully graph-capturable
// ---------------------------------------------------------------------------
extern "C" void kernel_launch(void* const* d_in, const int* in_sizes, int n_in,
                              void* d_out, int out_size)
{
    const float* x  = (const float*)d_in[0];
    const float* W1 = (const float*)d_in[1];
    const float* b1 = (const float*)d_in[2];
    const float* W2 = (const float*)d_in[3];
    const float* b2 = (const float*)d_in[4];
    const float* W3 = (const float*)d_in[5];
    const float* b3 = (const float*)d_in[6];
    const float* Wl = (const float*)d_in[7];
    const float* bl = (const float*)d_in[8];
    float* out = (float*)d_out;

    cudaFuncSetAttribute(ode_persistent,
                         cudaFuncAttributeMaxDynamicSharedMemorySize, SMEM_BYTES);

    ode_persistent<<<NBLOCKS, 256, SMEM_BYTES>>>(x, W1, b1, W2, b2, W3, b3);
    final_kernel<<<NTILES, 256>>>(Wl, bl, out);
}